// round 10
// baseline (speedup 1.0000x reference)
#include <cuda_runtime.h>
#include <cuda_fp16.h>
#include <mma.h>
#include <cstdint>

using namespace nvcuda;

#define NNODES 50000
#define NEDGES 800000
#define LN_EPS 1e-5f

#define SCAN_BS 512
#define SCAN_NB ((NNODES + SCAN_BS - 1) / SCAN_BS)   // 98
#define TB 256
#define GEMM_NB ((NNODES + 63) / 64)                 // 782
#define EDGE_NB ((NEDGES + TB - 1) / TB)             // 3125

// ---------------- scratch (static device globals; no runtime alloc) ----------
__device__ __align__(32) __half g_h16[NNODES * 128];    // GEMM output (fp16 messages)
__device__ __align__(32) __half g_feat16[NNODES * 128]; // LN output (fp16, next layer A)
__device__ __align__(32) __half g_w16_1[128 * 128];
__device__ __align__(32) __half g_w16_2[128 * 128];
__device__ __align__(32) __half g_w16_3[128 * 64];
__device__ float  g_deg[NNODES];      // weighted in-degree (memset 0; +1 self-loop at dinv)
__device__ float  g_dinv[NNODES];
__device__ int    g_cnt[NNODES];
__device__ int    g_off[NNODES + 1];
__device__ int    g_cur[NNODES];
__device__ int    g_bsum[SCAN_NB];
__device__ int    g_bpre[SCAN_NB];
__device__ __align__(16) int   g_csr_src[NEDGES];
__device__ __align__(16) float g_csr_nrm[NEDGES];

// ---------------- conversions -------------------------------------------------
__global__ void cvt_w_kernel(const float* __restrict__ W1, const float* __restrict__ W2,
                             const float* __restrict__ W3) {
    int i = blockIdx.x * blockDim.x + threadIdx.x;
    if (i < 16384) g_w16_1[i] = __float2half(W1[i]);
    else if (i < 32768) g_w16_2[i - 16384] = __float2half(W2[i - 16384]);
    else if (i < 40960) g_w16_3[i - 32768] = __float2half(W3[i - 32768]);
}

// ---------------- precompute bodies ------------------------------------------
__device__ __forceinline__ void count_body(const int* __restrict__ dst,
                                           const float* __restrict__ w, int blk) {
    int e = blk * TB + threadIdx.x;
    if (e < NEDGES) {
        int d = dst[e];
        atomicAdd(&g_deg[d], w[e]);    // separate arrays: atomics spread over
        atomicAdd(&g_cnt[d], 1);       // independent lines/LTS partitions
    }
}

// ---------------- tensor-core GEMM body --------------------------------------
template <int OUT, bool A32>
__device__ __forceinline__ void gemm_body(const void* __restrict__ Av,
                                          const __half* __restrict__ W,
                                          __half* __restrict__ H, int blk) {
    constexpr int IN = 128;
    constexpr int ALD = IN + 16;
    constexpr int CLD = OUT + 8;
    constexpr int COLW = OUT / 2;
    constexpr int NF = COLW / 16;
    constexpr int ABYTES = 64 * ALD * 2;
    constexpr int CBYTES = 64 * CLD * 4;
    constexpr int BUFB = (ABYTES > CBYTES) ? ABYTES : CBYTES;

    __shared__ __align__(32) char buf[BUFB];
    __half (*As)[ALD] = (__half(*)[ALD])buf;
    float (*Cs)[CLD] = (float(*)[CLD])buf;

    const int t = threadIdx.x;
    const int row0 = blk * 64;

    if (A32) {
        const float* A = (const float*)Av;
        for (int i = t; i < 64 * (IN / 4); i += 256) {
            int r = i >> 5;
            int kc = (i & 31) * 4;
            int gr = row0 + r;
            float4 v = make_float4(0.f, 0.f, 0.f, 0.f);
            if (gr < NNODES) v = *(const float4*)(A + (size_t)gr * IN + kc);
            __half2 a = __floats2half2_rn(v.x, v.y);
            __half2 b = __floats2half2_rn(v.z, v.w);
            uint2 u;
            u.x = *(uint32_t*)&a;
            u.y = *(uint32_t*)&b;
            *(uint2*)&As[r][kc] = u;
        }
    } else {
        const __half* A = (const __half*)Av;
        for (int i = t; i < 64 * (IN / 8); i += 256) {
            int r = i >> 4;
            int kc = (i & 15) * 8;
            int gr = row0 + r;
            uint4 v = make_uint4(0u, 0u, 0u, 0u);
            if (gr < NNODES) v = *(const uint4*)(A + (size_t)gr * IN + kc);
            *(uint4*)&As[r][kc] = v;
        }
    }
    __syncthreads();

    const int w = t >> 5;
    const int wr = w >> 1;
    const int wc = w & 1;

    wmma::fragment<wmma::accumulator, 16, 16, 16, float> cf[NF];
#pragma unroll
    for (int j = 0; j < NF; j++) wmma::fill_fragment(cf[j], 0.0f);

    wmma::fragment<wmma::matrix_a, 16, 16, 16, __half, wmma::row_major> af;
    wmma::fragment<wmma::matrix_b, 16, 16, 16, __half, wmma::row_major> bf;

#pragma unroll
    for (int k = 0; k < IN; k += 16) {
        wmma::load_matrix_sync(af, &As[wr * 16][k], ALD);
#pragma unroll
        for (int j = 0; j < NF; j++) {
            wmma::load_matrix_sync(bf, W + (size_t)k * OUT + wc * COLW + j * 16, OUT);
            wmma::mma_sync(cf[j], af, bf, cf[j]);
        }
    }

    __syncthreads();
#pragma unroll
    for (int j = 0; j < NF; j++)
        wmma::store_matrix_sync(&Cs[wr * 16][wc * COLW + j * 16], cf[j], CLD,
                                wmma::mem_row_major);
    __syncthreads();

    for (int i = t; i < 64 * (OUT / 2); i += 256) {
        int r = i / (OUT / 2);
        int c = (i % (OUT / 2)) * 2;
        int gr = row0 + r;
        if (gr < NNODES) {
            __half2 hv = __floats2half2_rn(Cs[r][c], Cs[r][c + 1]);
            *(__half2*)(H + (size_t)gr * OUT + c) = hv;
        }
    }
}

// fused: gemm1 (blocks [0,GEMM_NB)) + count (blocks [GEMM_NB, GEMM_NB+EDGE_NB))
__global__ void __launch_bounds__(256) fused_gemm1_count_kernel(
    const float* __restrict__ x, const int* __restrict__ dst,
    const float* __restrict__ ew) {
    if (blockIdx.x < GEMM_NB) {
        gemm_body<128, true>(x, g_w16_1, g_h16, blockIdx.x);
    } else {
        count_body(dst, ew, blockIdx.x - GEMM_NB);
    }
}

template <int OUT>
__global__ void __launch_bounds__(256) gemm_kernel(const __half* __restrict__ A,
                                                   const __half* __restrict__ W,
                                                   __half* __restrict__ H) {
    gemm_body<OUT, false>(A, W, H, blockIdx.x);
}

// ---------------- scan (3-phase; validated fastest) ---------------------------
__global__ void scan_block_kernel() {
    __shared__ int wsum[SCAN_BS / 32];
    int t = threadIdx.x;
    int lane = t & 31;
    int wid = t >> 5;
    int i = blockIdx.x * SCAN_BS + t;
    int v = (i < NNODES) ? g_cnt[i] : 0;

    int x = v;
#pragma unroll
    for (int o = 1; o < 32; o <<= 1) {
        int y = __shfl_up_sync(0xffffffffu, x, o);
        if (lane >= o) x += y;
    }
    if (lane == 31) wsum[wid] = x;
    __syncthreads();
    if (wid == 0) {
        int s = (lane < SCAN_BS / 32) ? wsum[lane] : 0;
#pragma unroll
        for (int o = 1; o < SCAN_BS / 32; o <<= 1) {
            int y = __shfl_up_sync(0xffffffffu, s, o);
            if (lane >= o) s += y;
        }
        if (lane < SCAN_BS / 32) wsum[lane] = s;
    }
    __syncthreads();
    int wpre = (wid == 0) ? 0 : wsum[wid - 1];
    int excl = wpre + x - v;
    if (i < NNODES) g_off[i] = excl;
    if (t == SCAN_BS - 1) g_bsum[blockIdx.x] = wpre + x;
}

__global__ void scan_tops_kernel() {
    int lane = threadIdx.x;
    int base = lane * 4;
    int v[4];
    int s = 0;
#pragma unroll
    for (int i = 0; i < 4; i++) {
        v[i] = (base + i < SCAN_NB) ? g_bsum[base + i] : 0;
        s += v[i];
    }
    int x = s;
#pragma unroll
    for (int o = 1; o < 32; o <<= 1) {
        int y = __shfl_up_sync(0xffffffffu, x, o);
        if (lane >= o) x += y;
    }
    int pre = x - s;
#pragma unroll
    for (int i = 0; i < 4; i++) {
        if (base + i < SCAN_NB) g_bpre[base + i] = pre;
        pre += v[i];
    }
}

__global__ void scan_add_kernel() {
    int i = blockIdx.x * SCAN_BS + threadIdx.x;
    if (i < NNODES) {
        int off = g_off[i] + g_bpre[blockIdx.x];
        g_off[i] = off;
        g_cur[i] = off;
        g_dinv[i] = rsqrtf(g_deg[i] + 1.0f);   // +1 = self-loop weight
    }
    if (i == 0) g_off[NNODES] = NEDGES;
}

__global__ void fill_kernel(const int* __restrict__ src, const int* __restrict__ dst,
                            const float* __restrict__ w) {
    int e = blockIdx.x * blockDim.x + threadIdx.x;
    if (e >= NEDGES) return;
    int s = src[e];
    int d = dst[e];
    float nm = g_dinv[s] * w[e] * g_dinv[d];
    int pos = atomicAdd(&g_cur[d], 1);
    g_csr_src[pos] = s;
    g_csr_nrm[pos] = nm;
}

// ------- fused: gather-aggregate (CSR, fp16 msgs) + self + bias + LN ---------
__device__ __forceinline__ float4 ld_h16_row(const __half* H, int row, int lane) {
    uint2 u = *(const uint2*)(H + (size_t)row * 128 + lane * 4);
    float2 a = __half22float2(*(__half2*)&u.x);
    float2 b = __half22float2(*(__half2*)&u.y);
    return make_float4(a.x, a.y, b.x, b.y);
}
__device__ __forceinline__ float2 ld_h16_row64(const __half* H, int row, int lane) {
    uint32_t u = *(const uint32_t*)(H + (size_t)row * 64 + lane * 2);
    return __half22float2(*(__half2*)&u);
}

template <int DIM, bool RELU, bool HALF_OUT>
__global__ void agg_ln_kernel(const __half* __restrict__ H, const float* __restrict__ b,
                              const float* __restrict__ gm, const float* __restrict__ bt,
                              void* __restrict__ Ov) {
    int gt = blockIdx.x * blockDim.x + threadIdx.x;
    int node = gt >> 5;
    if (node >= NNODES) return;
    int lane = gt & 31;

    float di = g_dinv[node];
    float d2 = di * di;
    int beg = g_off[node];
    int end = g_off[node + 1];

    if (DIM == 128) {
        int c = lane * 4;
        float4 hv = ld_h16_row(H, node, lane);
        float4 bv = *(const float4*)(b + c);
        float4 acc;
        acc.x = d2 * hv.x + bv.x;
        acc.y = d2 * hv.y + bv.y;
        acc.z = d2 * hv.z + bv.z;
        acc.w = d2 * hv.w + bv.w;

        int j = beg;
        // peel to 16B alignment for vector CSR loads
        for (; j < end && (j & 3); j++) {
            int s = __ldg(&g_csr_src[j]);
            float nm = __ldg(&g_csr_nrm[j]);
            float4 v = ld_h16_row(H, s, lane);
            acc.x += nm * v.x;
            acc.y += nm * v.y;
            acc.z += nm * v.z;
            acc.w += nm * v.w;
        }
        // 4 edges per iteration: src/nrm fetched with ONE int4 + ONE float4 LDG
        for (; j + 3 < end; j += 4) {
            int4 ss = __ldg((const int4*)&g_csr_src[j]);
            float4 nn = __ldg((const float4*)&g_csr_nrm[j]);
            float4 v0 = ld_h16_row(H, ss.x, lane);
            float4 v1 = ld_h16_row(H, ss.y, lane);
            float4 v2 = ld_h16_row(H, ss.z, lane);
            float4 v3 = ld_h16_row(H, ss.w, lane);
            acc.x += nn.x * v0.x + nn.y * v1.x + nn.z * v2.x + nn.w * v3.x;
            acc.y += nn.x * v0.y + nn.y * v1.y + nn.z * v2.y + nn.w * v3.y;
            acc.z += nn.x * v0.z + nn.y * v1.z + nn.z * v2.z + nn.w * v3.z;
            acc.w += nn.x * v0.w + nn.y * v1.w + nn.z * v2.w + nn.w * v3.w;
        }
        for (; j < end; j++) {
            int s = __ldg(&g_csr_src[j]);
            float nm = __ldg(&g_csr_nrm[j]);
            float4 v = ld_h16_row(H, s, lane);
            acc.x += nm * v.x;
            acc.y += nm * v.y;
            acc.z += nm * v.z;
            acc.w += nm * v.w;
        }

        float s1 = acc.x + acc.y + acc.z + acc.w;
        float s2 = acc.x * acc.x + acc.y * acc.y + acc.z * acc.z + acc.w * acc.w;
#pragma unroll
        for (int o = 16; o > 0; o >>= 1) {
            s1 += __shfl_xor_sync(0xffffffffu, s1, o);
            s2 += __shfl_xor_sync(0xffffffffu, s2, o);
        }
        float mean = s1 * (1.0f / 128.0f);
        float var = s2 * (1.0f / 128.0f) - mean * mean;
        float inv = rsqrtf(var + LN_EPS);
        float4 gv = *(const float4*)(gm + c);
        float4 tv = *(const float4*)(bt + c);
        float4 o4;
        o4.x = (acc.x - mean) * inv * gv.x + tv.x;
        o4.y = (acc.y - mean) * inv * gv.y + tv.y;
        o4.z = (acc.z - mean) * inv * gv.z + tv.z;
        o4.w = (acc.w - mean) * inv * gv.w + tv.w;
        if (RELU) {
            o4.x = fmaxf(o4.x, 0.0f);
            o4.y = fmaxf(o4.y, 0.0f);
            o4.z = fmaxf(o4.z, 0.0f);
            o4.w = fmaxf(o4.w, 0.0f);
        }
        if (HALF_OUT) {
            __half* O = (__half*)Ov;
            __half2 ha = __floats2half2_rn(o4.x, o4.y);
            __half2 hb = __floats2half2_rn(o4.z, o4.w);
            uint2 u;
            u.x = *(uint32_t*)&ha;
            u.y = *(uint32_t*)&hb;
            *(uint2*)(O + (size_t)node * 128 + c) = u;
        } else {
            float* O = (float*)Ov;
            *(float4*)(O + (size_t)node * 128 + c) = o4;
        }
    } else {   // DIM == 64
        int c = lane * 2;
        float2 hv = ld_h16_row64(H, node, lane);
        float2 bv = *(const float2*)(b + c);
        float2 acc;
        acc.x = d2 * hv.x + bv.x;
        acc.y = d2 * hv.y + bv.y;

        int j = beg;
        for (; j < end && (j & 3); j++) {
            int s = __ldg(&g_csr_src[j]);
            float nm = __ldg(&g_csr_nrm[j]);
            float2 v = ld_h16_row64(H, s, lane);
            acc.x += nm * v.x;
            acc.y += nm * v.y;
        }
        for (; j + 3 < end; j += 4) {
            int4 ss = __ldg((const int4*)&g_csr_src[j]);
            float4 nn = __ldg((const float4*)&g_csr_nrm[j]);
            float2 v0 = ld_h16_row64(H, ss.x, lane);
            float2 v1 = ld_h16_row64(H, ss.y, lane);
            float2 v2 = ld_h16_row64(H, ss.z, lane);
            float2 v3 = ld_h16_row64(H, ss.w, lane);
            acc.x += nn.x * v0.x + nn.y * v1.x + nn.z * v2.x + nn.w * v3.x;
            acc.y += nn.x * v0.y + nn.y * v1.y + nn.z * v2.y + nn.w * v3.y;
        }
        for (; j < end; j++) {
            int s = __ldg(&g_csr_src[j]);
            float nm = __ldg(&g_csr_nrm[j]);
            float2 v = ld_h16_row64(H, s, lane);
            acc.x += nm * v.x;
            acc.y += nm * v.y;
        }

        float s1 = acc.x + acc.y;
        float s2 = acc.x * acc.x + acc.y * acc.y;
#pragma unroll
        for (int o = 16; o > 0; o >>= 1) {
            s1 += __shfl_xor_sync(0xffffffffu, s1, o);
            s2 += __shfl_xor_sync(0xffffffffu, s2, o);
        }
        float mean = s1 * (1.0f / 64.0f);
        float var = s2 * (1.0f / 64.0f) - mean * mean;
        float inv = rsqrtf(var + LN_EPS);
        float2 gv = *(const float2*)(gm + c);
        float2 tv = *(const float2*)(bt + c);
        float2 o2;
        o2.x = (acc.x - mean) * inv * gv.x + tv.x;
        o2.y = (acc.y - mean) * inv * gv.y + tv.y;
        if (RELU) {
            o2.x = fmaxf(o2.x, 0.0f);
            o2.y = fmaxf(o2.y, 0.0f);
        }
        float* O = (float*)Ov;
        *(float2*)(O + (size_t)node * 64 + c) = o2;
    }
}

// ---------------- host launch -------------------------------------------------
extern "C" void kernel_launch(void* const* d_in, const int* in_sizes, int n_in,
                              void* d_out, int out_size) {
    const float* x  = (const float*)d_in[0];
    const int*   ei = (const int*)d_in[1];
    const float* ew = (const float*)d_in[2];
    const float* W1 = (const float*)d_in[3];
    const float* b1 = (const float*)d_in[4];
    const float* g1 = (const float*)d_in[5];
    const float* t1 = (const float*)d_in[6];
    const float* W2 = (const float*)d_in[7];
    const float* b2 = (const float*)d_in[8];
    const float* g2 = (const float*)d_in[9];
    const float* t2 = (const float*)d_in[10];
    const float* W3 = (const float*)d_in[11];
    const float* b3 = (const float*)d_in[12];
    const float* g3 = (const float*)d_in[13];
    const float* t3 = (const float*)d_in[14];
    const int* src = ei;
    const int* dst = ei + NEDGES;

    __half *h16, *feat16, *w16_2, *w16_3;
    float *deg;
    int *cnt;
    cudaGetSymbolAddress((void**)&h16, g_h16);
    cudaGetSymbolAddress((void**)&feat16, g_feat16);
    cudaGetSymbolAddress((void**)&w16_2, g_w16_2);
    cudaGetSymbolAddress((void**)&w16_3, g_w16_3);
    cudaGetSymbolAddress((void**)&deg, g_deg);
    cudaGetSymbolAddress((void**)&cnt, g_cnt);

    const int nblk_row = (NNODES * 32 + TB - 1) / TB;    // warp per node

    // precompute
    cudaMemsetAsync(deg, 0, NNODES * sizeof(float));
    cudaMemsetAsync(cnt, 0, NNODES * sizeof(int));
    cvt_w_kernel<<<(40960 + TB - 1) / TB, TB>>>(W1, W2, W3);
    // overlapped: layer-1 GEMM (independent) + edge counting
    fused_gemm1_count_kernel<<<GEMM_NB + EDGE_NB, TB>>>(x, dst, ew);
    scan_block_kernel<<<SCAN_NB, SCAN_BS>>>();
    scan_tops_kernel<<<1, 32>>>();
    scan_add_kernel<<<SCAN_NB, SCAN_BS>>>();
    fill_kernel<<<EDGE_NB, TB>>>(src, dst, ew);

    // layer 1 aggregation (gemm1 already done in fused kernel)
    agg_ln_kernel<128, true, true><<<nblk_row, TB>>>(h16, b1, g1, t1, feat16);

    // layer 2
    gemm_kernel<128><<<GEMM_NB, TB>>>(feat16, w16_2, h16);
    agg_ln_kernel<128, true, true><<<nblk_row, TB>>>(h16, b2, g2, t2, feat16);

    // layer 3 (dout = 64, no relu), fp32 output straight to d_out
    gemm_kernel<64><<<GEMM_NB, TB>>>(feat16, w16_3, h16);
    agg_ln_kernel<64, false, false><<<nblk_row, TB>>>(h16, b3, g3, t3, d_out);
}

// round 11
// speedup vs baseline: 1.5347x; 1.5347x over previous
#include <cuda_runtime.h>
#include <cuda_fp16.h>
#include <mma.h>
#include <cstdint>

using namespace nvcuda;

#define NNODES 50000
#define NEDGES 800000
#define LN_EPS 1e-5f

#define SCAN_BS 512
#define SCAN_NB ((NNODES + SCAN_BS - 1) / SCAN_BS)   // 98
#define TB 256
#define GEMM_NB ((NNODES + 63) / 64)                 // 782
#define EDGE_NB ((NEDGES + TB - 1) / TB)             // 3125

// ---------------- scratch (static device globals; no runtime alloc) ----------
__device__ __align__(32) __half g_h16[NNODES * 128];    // GEMM output (fp16 messages)
__device__ __align__(32) __half g_feat16[NNODES * 128]; // LN output (fp16, next layer A)
__device__ __align__(32) __half g_w16_1[128 * 128];
__device__ __align__(32) __half g_w16_2[128 * 128];
__device__ __align__(32) __half g_w16_3[128 * 64];
__device__ float  g_deg[NNODES];      // weighted in-degree (memset 0; +1 self-loop at dinv)
__device__ float  g_dinv[NNODES];
__device__ int    g_cnt[NNODES];
__device__ int    g_off[NNODES + 1];
__device__ int    g_cur[NNODES];
__device__ int    g_bsum[SCAN_NB];
__device__ int    g_bpre[SCAN_NB];
__device__ int    g_csr_src[NEDGES];
__device__ float  g_csr_nrm[NEDGES];

// ---------------- conversions -------------------------------------------------
__global__ void cvt_w_kernel(const float* __restrict__ W1, const float* __restrict__ W2,
                             const float* __restrict__ W3) {
    int i = blockIdx.x * blockDim.x + threadIdx.x;
    if (i < 16384) g_w16_1[i] = __float2half(W1[i]);
    else if (i < 32768) g_w16_2[i - 16384] = __float2half(W2[i - 16384]);
    else if (i < 40960) g_w16_3[i - 32768] = __float2half(W3[i - 32768]);
}

// ---------------- precompute bodies ------------------------------------------
__device__ __forceinline__ void count_body(const int* __restrict__ dst,
                                           const float* __restrict__ w, int blk) {
    int e = blk * TB + threadIdx.x;
    if (e < NEDGES) {
        int d = dst[e];
        atomicAdd(&g_deg[d], w[e]);    // separate arrays: atomics spread over
        atomicAdd(&g_cnt[d], 1);       // independent lines/LTS partitions
    }
}

// ---------------- tensor-core GEMM body --------------------------------------
template <int OUT, bool A32>
__device__ __forceinline__ void gemm_body(const void* __restrict__ Av,
                                          const __half* __restrict__ W,
                                          __half* __restrict__ H, int blk) {
    constexpr int IN = 128;
    constexpr int ALD = IN + 16;
    constexpr int CLD = OUT + 8;
    constexpr int COLW = OUT / 2;
    constexpr int NF = COLW / 16;
    constexpr int ABYTES = 64 * ALD * 2;
    constexpr int CBYTES = 64 * CLD * 4;
    constexpr int BUFB = (ABYTES > CBYTES) ? ABYTES : CBYTES;

    __shared__ __align__(32) char buf[BUFB];
    __half (*As)[ALD] = (__half(*)[ALD])buf;
    float (*Cs)[CLD] = (float(*)[CLD])buf;

    const int t = threadIdx.x;
    const int row0 = blk * 64;

    if (A32) {
        const float* A = (const float*)Av;
        for (int i = t; i < 64 * (IN / 4); i += 256) {
            int r = i >> 5;
            int kc = (i & 31) * 4;
            int gr = row0 + r;
            float4 v = make_float4(0.f, 0.f, 0.f, 0.f);
            if (gr < NNODES) v = *(const float4*)(A + (size_t)gr * IN + kc);
            __half2 a = __floats2half2_rn(v.x, v.y);
            __half2 b = __floats2half2_rn(v.z, v.w);
            uint2 u;
            u.x = *(uint32_t*)&a;
            u.y = *(uint32_t*)&b;
            *(uint2*)&As[r][kc] = u;
        }
    } else {
        const __half* A = (const __half*)Av;
        for (int i = t; i < 64 * (IN / 8); i += 256) {
            int r = i >> 4;
            int kc = (i & 15) * 8;
            int gr = row0 + r;
            uint4 v = make_uint4(0u, 0u, 0u, 0u);
            if (gr < NNODES) v = *(const uint4*)(A + (size_t)gr * IN + kc);
            *(uint4*)&As[r][kc] = v;
        }
    }
    __syncthreads();

    const int w = t >> 5;
    const int wr = w >> 1;
    const int wc = w & 1;

    wmma::fragment<wmma::accumulator, 16, 16, 16, float> cf[NF];
#pragma unroll
    for (int j = 0; j < NF; j++) wmma::fill_fragment(cf[j], 0.0f);

    wmma::fragment<wmma::matrix_a, 16, 16, 16, __half, wmma::row_major> af;
    wmma::fragment<wmma::matrix_b, 16, 16, 16, __half, wmma::row_major> bf;

#pragma unroll
    for (int k = 0; k < IN; k += 16) {
        wmma::load_matrix_sync(af, &As[wr * 16][k], ALD);
#pragma unroll
        for (int j = 0; j < NF; j++) {
            wmma::load_matrix_sync(bf, W + (size_t)k * OUT + wc * COLW + j * 16, OUT);
            wmma::mma_sync(cf[j], af, bf, cf[j]);
        }
    }

    __syncthreads();
#pragma unroll
    for (int j = 0; j < NF; j++)
        wmma::store_matrix_sync(&Cs[wr * 16][wc * COLW + j * 16], cf[j], CLD,
                                wmma::mem_row_major);
    __syncthreads();

    for (int i = t; i < 64 * (OUT / 2); i += 256) {
        int r = i / (OUT / 2);
        int c = (i % (OUT / 2)) * 2;
        int gr = row0 + r;
        if (gr < NNODES) {
            __half2 hv = __floats2half2_rn(Cs[r][c], Cs[r][c + 1]);
            *(__half2*)(H + (size_t)gr * OUT + c) = hv;
        }
    }
}

// fused: gemm1 (blocks [0,GEMM_NB)) + count (blocks [GEMM_NB, GEMM_NB+EDGE_NB))
__global__ void __launch_bounds__(256) fused_gemm1_count_kernel(
    const float* __restrict__ x, const int* __restrict__ dst,
    const float* __restrict__ ew) {
    if (blockIdx.x < GEMM_NB) {
        gemm_body<128, true>(x, g_w16_1, g_h16, blockIdx.x);
    } else {
        count_body(dst, ew, blockIdx.x - GEMM_NB);
    }
}

template <int OUT>
__global__ void __launch_bounds__(256) gemm_kernel(const __half* __restrict__ A,
                                                   const __half* __restrict__ W,
                                                   __half* __restrict__ H) {
    gemm_body<OUT, false>(A, W, H, blockIdx.x);
}

// ---------------- scan (3-phase; validated fastest) ---------------------------
__global__ void scan_block_kernel() {
    __shared__ int wsum[SCAN_BS / 32];
    int t = threadIdx.x;
    int lane = t & 31;
    int wid = t >> 5;
    int i = blockIdx.x * SCAN_BS + t;
    int v = (i < NNODES) ? g_cnt[i] : 0;

    int x = v;
#pragma unroll
    for (int o = 1; o < 32; o <<= 1) {
        int y = __shfl_up_sync(0xffffffffu, x, o);
        if (lane >= o) x += y;
    }
    if (lane == 31) wsum[wid] = x;
    __syncthreads();
    if (wid == 0) {
        int s = (lane < SCAN_BS / 32) ? wsum[lane] : 0;
#pragma unroll
        for (int o = 1; o < SCAN_BS / 32; o <<= 1) {
            int y = __shfl_up_sync(0xffffffffu, s, o);
            if (lane >= o) s += y;
        }
        if (lane < SCAN_BS / 32) wsum[lane] = s;
    }
    __syncthreads();
    int wpre = (wid == 0) ? 0 : wsum[wid - 1];
    int excl = wpre + x - v;
    if (i < NNODES) g_off[i] = excl;
    if (t == SCAN_BS - 1) g_bsum[blockIdx.x] = wpre + x;
}

__global__ void scan_tops_kernel() {
    int lane = threadIdx.x;
    int base = lane * 4;
    int v[4];
    int s = 0;
#pragma unroll
    for (int i = 0; i < 4; i++) {
        v[i] = (base + i < SCAN_NB) ? g_bsum[base + i] : 0;
        s += v[i];
    }
    int x = s;
#pragma unroll
    for (int o = 1; o < 32; o <<= 1) {
        int y = __shfl_up_sync(0xffffffffu, x, o);
        if (lane >= o) x += y;
    }
    int pre = x - s;
#pragma unroll
    for (int i = 0; i < 4; i++) {
        if (base + i < SCAN_NB) g_bpre[base + i] = pre;
        pre += v[i];
    }
}

__global__ void scan_add_kernel() {
    int i = blockIdx.x * SCAN_BS + threadIdx.x;
    if (i < NNODES) {
        int off = g_off[i] + g_bpre[blockIdx.x];
        g_off[i] = off;
        g_cur[i] = off;
        g_dinv[i] = rsqrtf(g_deg[i] + 1.0f);   // +1 = self-loop weight
    }
    if (i == 0) g_off[NNODES] = NEDGES;
}

__global__ void fill_kernel(const int* __restrict__ src, const int* __restrict__ dst,
                            const float* __restrict__ w) {
    int e = blockIdx.x * blockDim.x + threadIdx.x;
    if (e >= NEDGES) return;
    int s = src[e];
    int d = dst[e];
    float nm = g_dinv[s] * w[e] * g_dinv[d];
    int pos = atomicAdd(&g_cur[d], 1);
    g_csr_src[pos] = s;
    g_csr_nrm[pos] = nm;
}

// ------- fused: gather-aggregate (CSR, fp16 msgs) + self + bias + LN ---------
__device__ __forceinline__ float4 ld_h16_row(const __half* H, int row, int lane) {
    uint2 u = *(const uint2*)(H + (size_t)row * 128 + lane * 4);
    float2 a = __half22float2(*(__half2*)&u.x);
    float2 b = __half22float2(*(__half2*)&u.y);
    return make_float4(a.x, a.y, b.x, b.y);
}
__device__ __forceinline__ float2 ld_h16_row64(const __half* H, int row, int lane) {
    uint32_t u = *(const uint32_t*)(H + (size_t)row * 64 + lane * 2);
    return __half22float2(*(__half2*)&u);
}

template <int DIM, bool RELU, bool HALF_OUT>
__global__ void agg_ln_kernel(const __half* __restrict__ H, const float* __restrict__ b,
                              const float* __restrict__ gm, const float* __restrict__ bt,
                              void* __restrict__ Ov) {
    int gt = blockIdx.x * blockDim.x + threadIdx.x;
    int node = gt >> 5;
    if (node >= NNODES) return;
    int lane = gt & 31;

    float di = g_dinv[node];
    float d2 = di * di;
    int beg = g_off[node];
    int end = g_off[node + 1];

    if (DIM == 128) {
        int c = lane * 4;
        float4 hv = ld_h16_row(H, node, lane);
        float4 bv = *(const float4*)(b + c);
        float4 acc;
        acc.x = d2 * hv.x + bv.x;
        acc.y = d2 * hv.y + bv.y;
        acc.z = d2 * hv.z + bv.z;
        acc.w = d2 * hv.w + bv.w;

        int j = beg;
        for (; j + 3 < end; j += 4) {
            int s0 = __ldg(&g_csr_src[j]);
            int s1 = __ldg(&g_csr_src[j + 1]);
            int s2 = __ldg(&g_csr_src[j + 2]);
            int s3 = __ldg(&g_csr_src[j + 3]);
            float n0 = __ldg(&g_csr_nrm[j]);
            float n1 = __ldg(&g_csr_nrm[j + 1]);
            float n2 = __ldg(&g_csr_nrm[j + 2]);
            float n3 = __ldg(&g_csr_nrm[j + 3]);
            float4 v0 = ld_h16_row(H, s0, lane);
            float4 v1 = ld_h16_row(H, s1, lane);
            float4 v2 = ld_h16_row(H, s2, lane);
            float4 v3 = ld_h16_row(H, s3, lane);
            acc.x += n0 * v0.x + n1 * v1.x + n2 * v2.x + n3 * v3.x;
            acc.y += n0 * v0.y + n1 * v1.y + n2 * v2.y + n3 * v3.y;
            acc.z += n0 * v0.z + n1 * v1.z + n2 * v2.z + n3 * v3.z;
            acc.w += n0 * v0.w + n1 * v1.w + n2 * v2.w + n3 * v3.w;
        }
        for (; j < end; j++) {
            int s = __ldg(&g_csr_src[j]);
            float nm = __ldg(&g_csr_nrm[j]);
            float4 v = ld_h16_row(H, s, lane);
            acc.x += nm * v.x;
            acc.y += nm * v.y;
            acc.z += nm * v.z;
            acc.w += nm * v.w;
        }

        float s1 = acc.x + acc.y + acc.z + acc.w;
        float s2 = acc.x * acc.x + acc.y * acc.y + acc.z * acc.z + acc.w * acc.w;
#pragma unroll
        for (int o = 16; o > 0; o >>= 1) {
            s1 += __shfl_xor_sync(0xffffffffu, s1, o);
            s2 += __shfl_xor_sync(0xffffffffu, s2, o);
        }
        float mean = s1 * (1.0f / 128.0f);
        float var = s2 * (1.0f / 128.0f) - mean * mean;
        float inv = rsqrtf(var + LN_EPS);
        float4 gv = *(const float4*)(gm + c);
        float4 tv = *(const float4*)(bt + c);
        float4 o4;
        o4.x = (acc.x - mean) * inv * gv.x + tv.x;
        o4.y = (acc.y - mean) * inv * gv.y + tv.y;
        o4.z = (acc.z - mean) * inv * gv.z + tv.z;
        o4.w = (acc.w - mean) * inv * gv.w + tv.w;
        if (RELU) {
            o4.x = fmaxf(o4.x, 0.0f);
            o4.y = fmaxf(o4.y, 0.0f);
            o4.z = fmaxf(o4.z, 0.0f);
            o4.w = fmaxf(o4.w, 0.0f);
        }
        if (HALF_OUT) {
            __half* O = (__half*)Ov;
            __half2 ha = __floats2half2_rn(o4.x, o4.y);
            __half2 hb = __floats2half2_rn(o4.z, o4.w);
            uint2 u;
            u.x = *(uint32_t*)&ha;
            u.y = *(uint32_t*)&hb;
            *(uint2*)(O + (size_t)node * 128 + c) = u;
        } else {
            float* O = (float*)Ov;
            *(float4*)(O + (size_t)node * 128 + c) = o4;
        }
    } else {   // DIM == 64
        int c = lane * 2;
        float2 hv = ld_h16_row64(H, node, lane);
        float2 bv = *(const float2*)(b + c);
        float2 acc;
        acc.x = d2 * hv.x + bv.x;
        acc.y = d2 * hv.y + bv.y;

        int j = beg;
        for (; j + 3 < end; j += 4) {
            int s0 = __ldg(&g_csr_src[j]);
            int s1 = __ldg(&g_csr_src[j + 1]);
            int s2 = __ldg(&g_csr_src[j + 2]);
            int s3 = __ldg(&g_csr_src[j + 3]);
            float n0 = __ldg(&g_csr_nrm[j]);
            float n1 = __ldg(&g_csr_nrm[j + 1]);
            float n2 = __ldg(&g_csr_nrm[j + 2]);
            float n3 = __ldg(&g_csr_nrm[j + 3]);
            float2 v0 = ld_h16_row64(H, s0, lane);
            float2 v1 = ld_h16_row64(H, s1, lane);
            float2 v2 = ld_h16_row64(H, s2, lane);
            float2 v3 = ld_h16_row64(H, s3, lane);
            acc.x += n0 * v0.x + n1 * v1.x + n2 * v2.x + n3 * v3.x;
            acc.y += n0 * v0.y + n1 * v1.y + n2 * v2.y + n3 * v3.y;
        }
        for (; j < end; j++) {
            int s = __ldg(&g_csr_src[j]);
            float nm = __ldg(&g_csr_nrm[j]);
            float2 v = ld_h16_row64(H, s, lane);
            acc.x += nm * v.x;
            acc.y += nm * v.y;
        }

        float s1 = acc.x + acc.y;
        float s2 = acc.x * acc.x + acc.y * acc.y;
#pragma unroll
        for (int o = 16; o > 0; o >>= 1) {
            s1 += __shfl_xor_sync(0xffffffffu, s1, o);
            s2 += __shfl_xor_sync(0xffffffffu, s2, o);
        }
        float mean = s1 * (1.0f / 64.0f);
        float var = s2 * (1.0f / 64.0f) - mean * mean;
        float inv = rsqrtf(var + LN_EPS);
        float2 gv = *(const float2*)(gm + c);
        float2 tv = *(const float2*)(bt + c);
        float2 o2;
        o2.x = (acc.x - mean) * inv * gv.x + tv.x;
        o2.y = (acc.y - mean) * inv * gv.y + tv.y;
        if (RELU) {
            o2.x = fmaxf(o2.x, 0.0f);
            o2.y = fmaxf(o2.y, 0.0f);
        }
        float* O = (float*)Ov;
        *(float2*)(O + (size_t)node * 64 + c) = o2;
    }
}

// ---------------- host launch -------------------------------------------------
extern "C" void kernel_launch(void* const* d_in, const int* in_sizes, int n_in,
                              void* d_out, int out_size) {
    const float* x  = (const float*)d_in[0];
    const int*   ei = (const int*)d_in[1];
    const float* ew = (const float*)d_in[2];
    const float* W1 = (const float*)d_in[3];
    const float* b1 = (const float*)d_in[4];
    const float* g1 = (const float*)d_in[5];
    const float* t1 = (const float*)d_in[6];
    const float* W2 = (const float*)d_in[7];
    const float* b2 = (const float*)d_in[8];
    const float* g2 = (const float*)d_in[9];
    const float* t2 = (const float*)d_in[10];
    const float* W3 = (const float*)d_in[11];
    const float* b3 = (const float*)d_in[12];
    const float* g3 = (const float*)d_in[13];
    const float* t3 = (const float*)d_in[14];
    const int* src = ei;
    const int* dst = ei + NEDGES;

    __half *h16, *feat16, *w16_2, *w16_3;
    float *deg;
    int *cnt;
    cudaGetSymbolAddress((void**)&h16, g_h16);
    cudaGetSymbolAddress((void**)&feat16, g_feat16);
    cudaGetSymbolAddress((void**)&w16_2, g_w16_2);
    cudaGetSymbolAddress((void**)&w16_3, g_w16_3);
    cudaGetSymbolAddress((void**)&deg, g_deg);
    cudaGetSymbolAddress((void**)&cnt, g_cnt);

    const int nblk_row = (NNODES * 32 + TB - 1) / TB;    // warp per node

    // precompute
    cudaMemsetAsync(deg, 0, NNODES * sizeof(float));
    cudaMemsetAsync(cnt, 0, NNODES * sizeof(int));
    cvt_w_kernel<<<(40960 + TB - 1) / TB, TB>>>(W1, W2, W3);
    // overlapped: layer-1 GEMM (independent) + edge counting
    fused_gemm1_count_kernel<<<GEMM_NB + EDGE_NB, TB>>>(x, dst, ew);
    scan_block_kernel<<<SCAN_NB, SCAN_BS>>>();
    scan_tops_kernel<<<1, 32>>>();
    scan_add_kernel<<<SCAN_NB, SCAN_BS>>>();
    fill_kernel<<<EDGE_NB, TB>>>(src, dst, ew);

    // layer 1 aggregation (gemm1 already done in fused kernel)
    agg_ln_kernel<128, true, true><<<nblk_row, TB>>>(h16, b1, g1, t1, feat16);

    // layer 2
    gemm_kernel<128><<<GEMM_NB, TB>>>(feat16, w16_2, h16);
    agg_ln_kernel<128, true, true><<<nblk_row, TB>>>(h16, b2, g2, t2, feat16);

    // layer 3 (dout = 64, no relu), fp32 output straight to d_out
    gemm_kernel<64><<<GEMM_NB, TB>>>(feat16, w16_3, h16);
    agg_ln_kernel<64, false, false><<<nblk_row, TB>>>(h16, b3, g3, t3, d_out);
}

// round 12
// speedup vs baseline: 1.5525x; 1.0116x over previous
#include <cuda_runtime.h>
#include <cuda_fp16.h>
#include <mma.h>
#include <cstdint>

using namespace nvcuda;

#define NNODES 50000
#define NEDGES 800000
#define LN_EPS 1e-5f

#define SCAN_BS 512
#define SCAN_NB ((NNODES + SCAN_BS - 1) / SCAN_BS)   // 98
#define TB 256
#define GEMM_NB ((NNODES + 63) / 64)                 // 782
#define EDGE_NB ((NEDGES + TB - 1) / TB)             // 3125
#define INIT_NB ((2 * NNODES + TB - 1) / TB)         // 391

// ---------------- scratch (static device globals; no runtime alloc) ----------
__device__ __align__(32) __half g_h16[NNODES * 128];    // GEMM output (fp16 messages)
__device__ __align__(32) __half g_feat16[NNODES * 128]; // LN output (fp16, next layer A)
__device__ __align__(32) __half g_w16_1[128 * 128];
__device__ __align__(32) __half g_w16_2[128 * 128];
__device__ __align__(32) __half g_w16_3[128 * 64];
__device__ __align__(16) int g_zeroed[2 * NNODES];  // [deg(float) | cnt(int)], zeroed by init
#define G_DEG ((float*)g_zeroed)
#define G_CNT (g_zeroed + NNODES)
__device__ float  g_dinv[NNODES];
__device__ int    g_off[NNODES + 1];
__device__ int    g_cur[NNODES];
__device__ int    g_bsum[SCAN_NB];
__device__ int    g_csr_src[NEDGES];
__device__ float  g_csr_nrm[NEDGES];

// ---------------- init: zero deg/cnt + convert weights to fp16 ---------------
__global__ void init_kernel(const float* __restrict__ W1, const float* __restrict__ W2,
                            const float* __restrict__ W3) {
    int i = blockIdx.x * blockDim.x + threadIdx.x;
    if (i < 2 * NNODES) g_zeroed[i] = 0;
    if (i < 16384) g_w16_1[i] = __float2half(W1[i]);
    else if (i < 32768) g_w16_2[i - 16384] = __float2half(W2[i - 16384]);
    else if (i < 40960) g_w16_3[i - 32768] = __float2half(W3[i - 32768]);
}

// ---------------- precompute bodies ------------------------------------------
__device__ __forceinline__ void count_body(const int* __restrict__ dst,
                                           const float* __restrict__ w, int blk) {
    int e = blk * TB + threadIdx.x;
    if (e < NEDGES) {
        int d = dst[e];
        atomicAdd(&G_DEG[d], w[e]);    // separate halves: atomics spread over
        atomicAdd(&G_CNT[d], 1);       // independent lines/LTS partitions
    }
}

// ---------------- tensor-core GEMM body --------------------------------------
template <int OUT, bool A32>
__device__ __forceinline__ void gemm_body(const void* __restrict__ Av,
                                          const __half* __restrict__ W,
                                          __half* __restrict__ H, int blk) {
    constexpr int IN = 128;
    constexpr int ALD = IN + 16;
    constexpr int CLD = OUT + 8;
    constexpr int COLW = OUT / 2;
    constexpr int NF = COLW / 16;
    constexpr int ABYTES = 64 * ALD * 2;
    constexpr int CBYTES = 64 * CLD * 4;
    constexpr int BUFB = (ABYTES > CBYTES) ? ABYTES : CBYTES;

    __shared__ __align__(32) char buf[BUFB];
    __half (*As)[ALD] = (__half(*)[ALD])buf;
    float (*Cs)[CLD] = (float(*)[CLD])buf;

    const int t = threadIdx.x;
    const int row0 = blk * 64;

    if (A32) {
        const float* A = (const float*)Av;
        for (int i = t; i < 64 * (IN / 4); i += 256) {
            int r = i >> 5;
            int kc = (i & 31) * 4;
            int gr = row0 + r;
            float4 v = make_float4(0.f, 0.f, 0.f, 0.f);
            if (gr < NNODES) v = *(const float4*)(A + (size_t)gr * IN + kc);
            __half2 a = __floats2half2_rn(v.x, v.y);
            __half2 b = __floats2half2_rn(v.z, v.w);
            uint2 u;
            u.x = *(uint32_t*)&a;
            u.y = *(uint32_t*)&b;
            *(uint2*)&As[r][kc] = u;
        }
    } else {
        const __half* A = (const __half*)Av;
        for (int i = t; i < 64 * (IN / 8); i += 256) {
            int r = i >> 4;
            int kc = (i & 15) * 8;
            int gr = row0 + r;
            uint4 v = make_uint4(0u, 0u, 0u, 0u);
            if (gr < NNODES) v = *(const uint4*)(A + (size_t)gr * IN + kc);
            *(uint4*)&As[r][kc] = v;
        }
    }
    __syncthreads();

    const int w = t >> 5;
    const int wr = w >> 1;
    const int wc = w & 1;

    wmma::fragment<wmma::accumulator, 16, 16, 16, float> cf[NF];
#pragma unroll
    for (int j = 0; j < NF; j++) wmma::fill_fragment(cf[j], 0.0f);

    wmma::fragment<wmma::matrix_a, 16, 16, 16, __half, wmma::row_major> af;
    wmma::fragment<wmma::matrix_b, 16, 16, 16, __half, wmma::row_major> bf;

#pragma unroll
    for (int k = 0; k < IN; k += 16) {
        wmma::load_matrix_sync(af, &As[wr * 16][k], ALD);
#pragma unroll
        for (int j = 0; j < NF; j++) {
            wmma::load_matrix_sync(bf, W + (size_t)k * OUT + wc * COLW + j * 16, OUT);
            wmma::mma_sync(cf[j], af, bf, cf[j]);
        }
    }

    __syncthreads();
#pragma unroll
    for (int j = 0; j < NF; j++)
        wmma::store_matrix_sync(&Cs[wr * 16][wc * COLW + j * 16], cf[j], CLD,
                                wmma::mem_row_major);
    __syncthreads();

    for (int i = t; i < 64 * (OUT / 2); i += 256) {
        int r = i / (OUT / 2);
        int c = (i % (OUT / 2)) * 2;
        int gr = row0 + r;
        if (gr < NNODES) {
            __half2 hv = __floats2half2_rn(Cs[r][c], Cs[r][c + 1]);
            *(__half2*)(H + (size_t)gr * OUT + c) = hv;
        }
    }
}

// fused: gemm1 (blocks [0,GEMM_NB)) + count (blocks [GEMM_NB, GEMM_NB+EDGE_NB))
__global__ void __launch_bounds__(256) fused_gemm1_count_kernel(
    const float* __restrict__ x, const int* __restrict__ dst,
    const float* __restrict__ ew) {
    if (blockIdx.x < GEMM_NB) {
        gemm_body<128, true>(x, g_w16_1, g_h16, blockIdx.x);
    } else {
        count_body(dst, ew, blockIdx.x - GEMM_NB);
    }
}

template <int OUT>
__global__ void __launch_bounds__(256) gemm_kernel(const __half* __restrict__ A,
                                                   const __half* __restrict__ W,
                                                   __half* __restrict__ H) {
    gemm_body<OUT, false>(A, W, H, blockIdx.x);
}

// ---------------- scan --------------------------------------------------------
__global__ void scan_block_kernel() {
    __shared__ int wsum[SCAN_BS / 32];
    int t = threadIdx.x;
    int lane = t & 31;
    int wid = t >> 5;
    int i = blockIdx.x * SCAN_BS + t;
    int v = (i < NNODES) ? G_CNT[i] : 0;

    int x = v;
#pragma unroll
    for (int o = 1; o < 32; o <<= 1) {
        int y = __shfl_up_sync(0xffffffffu, x, o);
        if (lane >= o) x += y;
    }
    if (lane == 31) wsum[wid] = x;
    __syncthreads();
    if (wid == 0) {
        int s = (lane < SCAN_BS / 32) ? wsum[lane] : 0;
#pragma unroll
        for (int o = 1; o < SCAN_BS / 32; o <<= 1) {
            int y = __shfl_up_sync(0xffffffffu, s, o);
            if (lane >= o) s += y;
        }
        if (lane < SCAN_BS / 32) wsum[lane] = s;
    }
    __syncthreads();
    int wpre = (wid == 0) ? 0 : wsum[wid - 1];
    int excl = wpre + x - v;
    if (i < NNODES) g_off[i] = excl;
    if (t == SCAN_BS - 1) g_bsum[blockIdx.x] = wpre + x;
}

// scan_add with INLINE tops: each block warp-reduces g_bsum[0..bid) itself.
__global__ void scan_add_kernel() {
    __shared__ int s_pre;
    const int bid = blockIdx.x;
    if (threadIdx.x < 32) {
        int lane = threadIdx.x;
        int sum = 0;
        for (int k = lane; k < bid; k += 32) sum += g_bsum[k];
#pragma unroll
        for (int o = 16; o > 0; o >>= 1)
            sum += __shfl_xor_sync(0xffffffffu, sum, o);
        if (lane == 0) s_pre = sum;
    }
    __syncthreads();
    int i = bid * SCAN_BS + threadIdx.x;
    if (i < NNODES) {
        int off = g_off[i] + s_pre;
        g_off[i] = off;
        g_cur[i] = off;
        g_dinv[i] = rsqrtf(G_DEG[i] + 1.0f);   // +1 = self-loop weight
    }
    if (i == 0) g_off[NNODES] = NEDGES;
}

__global__ void fill_kernel(const int* __restrict__ src, const int* __restrict__ dst,
                            const float* __restrict__ w) {
    int e = blockIdx.x * blockDim.x + threadIdx.x;
    if (e >= NEDGES) return;
    int s = src[e];
    int d = dst[e];
    float nm = g_dinv[s] * w[e] * g_dinv[d];
    int pos = atomicAdd(&g_cur[d], 1);
    g_csr_src[pos] = s;
    g_csr_nrm[pos] = nm;
}

// ------- fused: gather-aggregate (CSR, fp16 msgs) + self + bias + LN ---------
__device__ __forceinline__ float4 ld_h16_row(const __half* H, int row, int lane) {
    uint2 u = *(const uint2*)(H + (size_t)row * 128 + lane * 4);
    float2 a = __half22float2(*(__half2*)&u.x);
    float2 b = __half22float2(*(__half2*)&u.y);
    return make_float4(a.x, a.y, b.x, b.y);
}
__device__ __forceinline__ float2 ld_h16_row64(const __half* H, int row, int lane) {
    uint32_t u = *(const uint32_t*)(H + (size_t)row * 64 + lane * 2);
    return __half22float2(*(__half2*)&u);
}

template <int DIM, bool RELU, bool HALF_OUT>
__global__ void agg_ln_kernel(const __half* __restrict__ H, const float* __restrict__ b,
                              const float* __restrict__ gm, const float* __restrict__ bt,
                              void* __restrict__ Ov) {
    int gt = blockIdx.x * blockDim.x + threadIdx.x;
    int node = gt >> 5;
    if (node >= NNODES) return;
    int lane = gt & 31;

    float di = g_dinv[node];
    float d2 = di * di;
    int beg = g_off[node];
    int end = g_off[node + 1];

    if (DIM == 128) {
        int c = lane * 4;
        float4 hv = ld_h16_row(H, node, lane);
        float4 bv = *(const float4*)(b + c);
        float4 acc;
        acc.x = d2 * hv.x + bv.x;
        acc.y = d2 * hv.y + bv.y;
        acc.z = d2 * hv.z + bv.z;
        acc.w = d2 * hv.w + bv.w;

        int j = beg;
        for (; j + 3 < end; j += 4) {
            int s0 = __ldg(&g_csr_src[j]);
            int s1 = __ldg(&g_csr_src[j + 1]);
            int s2 = __ldg(&g_csr_src[j + 2]);
            int s3 = __ldg(&g_csr_src[j + 3]);
            float n0 = __ldg(&g_csr_nrm[j]);
            float n1 = __ldg(&g_csr_nrm[j + 1]);
            float n2 = __ldg(&g_csr_nrm[j + 2]);
            float n3 = __ldg(&g_csr_nrm[j + 3]);
            float4 v0 = ld_h16_row(H, s0, lane);
            float4 v1 = ld_h16_row(H, s1, lane);
            float4 v2 = ld_h16_row(H, s2, lane);
            float4 v3 = ld_h16_row(H, s3, lane);
            acc.x += n0 * v0.x + n1 * v1.x + n2 * v2.x + n3 * v3.x;
            acc.y += n0 * v0.y + n1 * v1.y + n2 * v2.y + n3 * v3.y;
            acc.z += n0 * v0.z + n1 * v1.z + n2 * v2.z + n3 * v3.z;
            acc.w += n0 * v0.w + n1 * v1.w + n2 * v2.w + n3 * v3.w;
        }
        for (; j < end; j++) {
            int s = __ldg(&g_csr_src[j]);
            float nm = __ldg(&g_csr_nrm[j]);
            float4 v = ld_h16_row(H, s, lane);
            acc.x += nm * v.x;
            acc.y += nm * v.y;
            acc.z += nm * v.z;
            acc.w += nm * v.w;
        }

        float s1 = acc.x + acc.y + acc.z + acc.w;
        float s2 = acc.x * acc.x + acc.y * acc.y + acc.z * acc.z + acc.w * acc.w;
#pragma unroll
        for (int o = 16; o > 0; o >>= 1) {
            s1 += __shfl_xor_sync(0xffffffffu, s1, o);
            s2 += __shfl_xor_sync(0xffffffffu, s2, o);
        }
        float mean = s1 * (1.0f / 128.0f);
        float var = s2 * (1.0f / 128.0f) - mean * mean;
        float inv = rsqrtf(var + LN_EPS);
        float4 gv = *(const float4*)(gm + c);
        float4 tv = *(const float4*)(bt + c);
        float4 o4;
        o4.x = (acc.x - mean) * inv * gv.x + tv.x;
        o4.y = (acc.y - mean) * inv * gv.y + tv.y;
        o4.z = (acc.z - mean) * inv * gv.z + tv.z;
        o4.w = (acc.w - mean) * inv * gv.w + tv.w;
        if (RELU) {
            o4.x = fmaxf(o4.x, 0.0f);
            o4.y = fmaxf(o4.y, 0.0f);
            o4.z = fmaxf(o4.z, 0.0f);
            o4.w = fmaxf(o4.w, 0.0f);
        }
        if (HALF_OUT) {
            __half* O = (__half*)Ov;
            __half2 ha = __floats2half2_rn(o4.x, o4.y);
            __half2 hb = __floats2half2_rn(o4.z, o4.w);
            uint2 u;
            u.x = *(uint32_t*)&ha;
            u.y = *(uint32_t*)&hb;
            *(uint2*)(O + (size_t)node * 128 + c) = u;
        } else {
            float* O = (float*)Ov;
            *(float4*)(O + (size_t)node * 128 + c) = o4;
        }
    } else {   // DIM == 64
        int c = lane * 2;
        float2 hv = ld_h16_row64(H, node, lane);
        float2 bv = *(const float2*)(b + c);
        float2 acc;
        acc.x = d2 * hv.x + bv.x;
        acc.y = d2 * hv.y + bv.y;

        int j = beg;
        for (; j + 3 < end; j += 4) {
            int s0 = __ldg(&g_csr_src[j]);
            int s1 = __ldg(&g_csr_src[j + 1]);
            int s2 = __ldg(&g_csr_src[j + 2]);
            int s3 = __ldg(&g_csr_src[j + 3]);
            float n0 = __ldg(&g_csr_nrm[j]);
            float n1 = __ldg(&g_csr_nrm[j + 1]);
            float n2 = __ldg(&g_csr_nrm[j + 2]);
            float n3 = __ldg(&g_csr_nrm[j + 3]);
            float2 v0 = ld_h16_row64(H, s0, lane);
            float2 v1 = ld_h16_row64(H, s1, lane);
            float2 v2 = ld_h16_row64(H, s2, lane);
            float2 v3 = ld_h16_row64(H, s3, lane);
            acc.x += n0 * v0.x + n1 * v1.x + n2 * v2.x + n3 * v3.x;
            acc.y += n0 * v0.y + n1 * v1.y + n2 * v2.y + n3 * v3.y;
        }
        for (; j < end; j++) {
            int s = __ldg(&g_csr_src[j]);
            float nm = __ldg(&g_csr_nrm[j]);
            float2 v = ld_h16_row64(H, s, lane);
            acc.x += nm * v.x;
            acc.y += nm * v.y;
        }

        float s1 = acc.x + acc.y;
        float s2 = acc.x * acc.x + acc.y * acc.y;
#pragma unroll
        for (int o = 16; o > 0; o >>= 1) {
            s1 += __shfl_xor_sync(0xffffffffu, s1, o);
            s2 += __shfl_xor_sync(0xffffffffu, s2, o);
        }
        float mean = s1 * (1.0f / 64.0f);
        float var = s2 * (1.0f / 64.0f) - mean * mean;
        float inv = rsqrtf(var + LN_EPS);
        float2 gv = *(const float2*)(gm + c);
        float2 tv = *(const float2*)(bt + c);
        float2 o2;
        o2.x = (acc.x - mean) * inv * gv.x + tv.x;
        o2.y = (acc.y - mean) * inv * gv.y + tv.y;
        if (RELU) {
            o2.x = fmaxf(o2.x, 0.0f);
            o2.y = fmaxf(o2.y, 0.0f);
        }
        float* O = (float*)Ov;
        *(float2*)(O + (size_t)node * 64 + c) = o2;
    }
}

// ---------------- host launch -------------------------------------------------
extern "C" void kernel_launch(void* const* d_in, const int* in_sizes, int n_in,
                              void* d_out, int out_size) {
    const float* x  = (const float*)d_in[0];
    const int*   ei = (const int*)d_in[1];
    const float* ew = (const float*)d_in[2];
    const float* W1 = (const float*)d_in[3];
    const float* b1 = (const float*)d_in[4];
    const float* g1 = (const float*)d_in[5];
    const float* t1 = (const float*)d_in[6];
    const float* W2 = (const float*)d_in[7];
    const float* b2 = (const float*)d_in[8];
    const float* g2 = (const float*)d_in[9];
    const float* t2 = (const float*)d_in[10];
    const float* W3 = (const float*)d_in[11];
    const float* b3 = (const float*)d_in[12];
    const float* g3 = (const float*)d_in[13];
    const float* t3 = (const float*)d_in[14];
    const int* src = ei;
    const int* dst = ei + NEDGES;

    __half *h16, *feat16, *w16_2, *w16_3;
    cudaGetSymbolAddress((void**)&h16, g_h16);
    cudaGetSymbolAddress((void**)&feat16, g_feat16);
    cudaGetSymbolAddress((void**)&w16_2, g_w16_2);
    cudaGetSymbolAddress((void**)&w16_3, g_w16_3);

    const int nblk_row = (NNODES * 32 + TB - 1) / TB;    // warp per node

    // precompute (5 launches before agg1 -> ncu -s 5 captures agg1)
    init_kernel<<<INIT_NB, TB>>>(W1, W2, W3);
    fused_gemm1_count_kernel<<<GEMM_NB + EDGE_NB, TB>>>(x, dst, ew);
    scan_block_kernel<<<SCAN_NB, SCAN_BS>>>();
    scan_add_kernel<<<SCAN_NB, SCAN_BS>>>();
    fill_kernel<<<EDGE_NB, TB>>>(src, dst, ew);

    // layer 1 aggregation (gemm1 already done in fused kernel)
    agg_ln_kernel<128, true, true><<<nblk_row, TB>>>(h16, b1, g1, t1, feat16);

    // layer 2
    gemm_kernel<128><<<GEMM_NB, TB>>>(feat16, w16_2, h16);
    agg_ln_kernel<128, true, true><<<nblk_row, TB>>>(h16, b2, g2, t2, feat16);

    // layer 3 (dout = 64, no relu), fp32 output straight to d_out
    gemm_kernel<64><<<GEMM_NB, TB>>>(feat16, w16_3, h16);
    agg_ln_kernel<64, false, false><<<nblk_row, TB>>>(h16, b3, g3, t3, d_out);
}

// round 13
// speedup vs baseline: 1.6056x; 1.0342x over previous
#include <cuda_runtime.h>
#include <cuda_fp16.h>
#include <mma.h>
#include <cstdint>

using namespace nvcuda;

#define NNODES 50000
#define NEDGES 800000
#define LN_EPS 1e-5f

#define SCAN_BS 512
#define SCAN_NB ((NNODES + SCAN_BS - 1) / SCAN_BS)   // 98
#define TB 256
#define GEMM_NB ((NNODES + 63) / 64)                 // 782
#define EDGE_NB ((NEDGES + TB - 1) / TB)             // 3125
#define INIT_NB ((2 * NNODES + TB - 1) / TB)         // 391

// ---------------- scratch (static device globals; no runtime alloc) ----------
__device__ __align__(32) __half g_h16[NNODES * 128];    // GEMM output (fp16 messages)
__device__ __align__(32) __half g_feat16[NNODES * 128]; // LN output (fp16, next layer A)
__device__ __align__(32) __half g_w16_1[128 * 128];
__device__ __align__(32) __half g_w16_2[128 * 128];
__device__ __align__(32) __half g_w16_3[128 * 64];
__device__ __align__(16) int g_zeroed[2 * NNODES];  // [deg(float) | cnt(int)], zeroed by init
#define G_DEG ((float*)g_zeroed)
#define G_CNT (g_zeroed + NNODES)
__device__ float  g_dinv[NNODES];
__device__ int    g_off[NNODES + 1];
__device__ int    g_cur[NNODES];
__device__ int    g_bsum[SCAN_NB];
__device__ unsigned g_csr[NEDGES];   // packed: low16 = src, high16 = fp16 norm

// ---------------- init: zero deg/cnt + convert weights to fp16 ---------------
__global__ void init_kernel(const float* __restrict__ W1, const float* __restrict__ W2,
                            const float* __restrict__ W3) {
    int i = blockIdx.x * blockDim.x + threadIdx.x;
    if (i < 2 * NNODES) g_zeroed[i] = 0;
    if (i < 16384) g_w16_1[i] = __float2half(W1[i]);
    else if (i < 32768) g_w16_2[i - 16384] = __float2half(W2[i - 16384]);
    else if (i < 40960) g_w16_3[i - 32768] = __float2half(W3[i - 32768]);
}

// ---------------- precompute bodies ------------------------------------------
__device__ __forceinline__ void count_body(const int* __restrict__ dst,
                                           const float* __restrict__ w, int blk) {
    int e = blk * TB + threadIdx.x;
    if (e < NEDGES) {
        int d = dst[e];
        atomicAdd(&G_DEG[d], w[e]);    // separate halves: atomics spread over
        atomicAdd(&G_CNT[d], 1);       // independent lines/LTS partitions
    }
}

// ---------------- tensor-core GEMM body --------------------------------------
template <int OUT, bool A32>
__device__ __forceinline__ void gemm_body(const void* __restrict__ Av,
                                          const __half* __restrict__ W,
                                          __half* __restrict__ H, int blk) {
    constexpr int IN = 128;
    constexpr int ALD = IN + 16;
    constexpr int CLD = OUT + 8;
    constexpr int COLW = OUT / 2;
    constexpr int NF = COLW / 16;
    constexpr int ABYTES = 64 * ALD * 2;
    constexpr int CBYTES = 64 * CLD * 4;
    constexpr int BUFB = (ABYTES > CBYTES) ? ABYTES : CBYTES;

    __shared__ __align__(32) char buf[BUFB];
    __half (*As)[ALD] = (__half(*)[ALD])buf;
    float (*Cs)[CLD] = (float(*)[CLD])buf;

    const int t = threadIdx.x;
    const int row0 = blk * 64;

    if (A32) {
        const float* A = (const float*)Av;
        for (int i = t; i < 64 * (IN / 4); i += 256) {
            int r = i >> 5;
            int kc = (i & 31) * 4;
            int gr = row0 + r;
            float4 v = make_float4(0.f, 0.f, 0.f, 0.f);
            if (gr < NNODES) v = *(const float4*)(A + (size_t)gr * IN + kc);
            __half2 a = __floats2half2_rn(v.x, v.y);
            __half2 b = __floats2half2_rn(v.z, v.w);
            uint2 u;
            u.x = *(uint32_t*)&a;
            u.y = *(uint32_t*)&b;
            *(uint2*)&As[r][kc] = u;
        }
    } else {
        const __half* A = (const __half*)Av;
        for (int i = t; i < 64 * (IN / 8); i += 256) {
            int r = i >> 4;
            int kc = (i & 15) * 8;
            int gr = row0 + r;
            uint4 v = make_uint4(0u, 0u, 0u, 0u);
            if (gr < NNODES) v = *(const uint4*)(A + (size_t)gr * IN + kc);
            *(uint4*)&As[r][kc] = v;
        }
    }
    __syncthreads();

    const int w = t >> 5;
    const int wr = w >> 1;
    const int wc = w & 1;

    wmma::fragment<wmma::accumulator, 16, 16, 16, float> cf[NF];
#pragma unroll
    for (int j = 0; j < NF; j++) wmma::fill_fragment(cf[j], 0.0f);

    wmma::fragment<wmma::matrix_a, 16, 16, 16, __half, wmma::row_major> af;
    wmma::fragment<wmma::matrix_b, 16, 16, 16, __half, wmma::row_major> bf;

#pragma unroll
    for (int k = 0; k < IN; k += 16) {
        wmma::load_matrix_sync(af, &As[wr * 16][k], ALD);
#pragma unroll
        for (int j = 0; j < NF; j++) {
            wmma::load_matrix_sync(bf, W + (size_t)k * OUT + wc * COLW + j * 16, OUT);
            wmma::mma_sync(cf[j], af, bf, cf[j]);
        }
    }

    __syncthreads();
#pragma unroll
    for (int j = 0; j < NF; j++)
        wmma::store_matrix_sync(&Cs[wr * 16][wc * COLW + j * 16], cf[j], CLD,
                                wmma::mem_row_major);
    __syncthreads();

    for (int i = t; i < 64 * (OUT / 2); i += 256) {
        int r = i / (OUT / 2);
        int c = (i % (OUT / 2)) * 2;
        int gr = row0 + r;
        if (gr < NNODES) {
            __half2 hv = __floats2half2_rn(Cs[r][c], Cs[r][c + 1]);
            *(__half2*)(H + (size_t)gr * OUT + c) = hv;
        }
    }
}

// fused: gemm1 (blocks [0,GEMM_NB)) + count (blocks [GEMM_NB, GEMM_NB+EDGE_NB))
__global__ void __launch_bounds__(256) fused_gemm1_count_kernel(
    const float* __restrict__ x, const int* __restrict__ dst,
    const float* __restrict__ ew) {
    if (blockIdx.x < GEMM_NB) {
        gemm_body<128, true>(x, g_w16_1, g_h16, blockIdx.x);
    } else {
        count_body(dst, ew, blockIdx.x - GEMM_NB);
    }
}

template <int OUT>
__global__ void __launch_bounds__(256) gemm_kernel(const __half* __restrict__ A,
                                                   const __half* __restrict__ W,
                                                   __half* __restrict__ H) {
    gemm_body<OUT, false>(A, W, H, blockIdx.x);
}

// ---------------- scan --------------------------------------------------------
__global__ void scan_block_kernel() {
    __shared__ int wsum[SCAN_BS / 32];
    int t = threadIdx.x;
    int lane = t & 31;
    int wid = t >> 5;
    int i = blockIdx.x * SCAN_BS + t;
    int v = (i < NNODES) ? G_CNT[i] : 0;

    int x = v;
#pragma unroll
    for (int o = 1; o < 32; o <<= 1) {
        int y = __shfl_up_sync(0xffffffffu, x, o);
        if (lane >= o) x += y;
    }
    if (lane == 31) wsum[wid] = x;
    __syncthreads();
    if (wid == 0) {
        int s = (lane < SCAN_BS / 32) ? wsum[lane] : 0;
#pragma unroll
        for (int o = 1; o < SCAN_BS / 32; o <<= 1) {
            int y = __shfl_up_sync(0xffffffffu, s, o);
            if (lane >= o) s += y;
        }
        if (lane < SCAN_BS / 32) wsum[lane] = s;
    }
    __syncthreads();
    int wpre = (wid == 0) ? 0 : wsum[wid - 1];
    int excl = wpre + x - v;
    if (i < NNODES) g_off[i] = excl;
    if (t == SCAN_BS - 1) g_bsum[blockIdx.x] = wpre + x;
}

// scan_add with INLINE tops: each block warp-reduces g_bsum[0..bid) itself.
__global__ void scan_add_kernel() {
    __shared__ int s_pre;
    const int bid = blockIdx.x;
    if (threadIdx.x < 32) {
        int lane = threadIdx.x;
        int sum = 0;
        for (int k = lane; k < bid; k += 32) sum += g_bsum[k];
#pragma unroll
        for (int o = 16; o > 0; o >>= 1)
            sum += __shfl_xor_sync(0xffffffffu, sum, o);
        if (lane == 0) s_pre = sum;
    }
    __syncthreads();
    int i = bid * SCAN_BS + threadIdx.x;
    if (i < NNODES) {
        int off = g_off[i] + s_pre;
        g_off[i] = off;
        g_cur[i] = off;
        g_dinv[i] = rsqrtf(G_DEG[i] + 1.0f);   // +1 = self-loop weight
    }
    if (i == 0) g_off[NNODES] = NEDGES;
}

// fill: pack {fp16 norm | src16} into one word -> single 4B random store
__global__ void fill_kernel(const int* __restrict__ src, const int* __restrict__ dst,
                            const float* __restrict__ w) {
    int e = blockIdx.x * blockDim.x + threadIdx.x;
    if (e >= NEDGES) return;
    int s = src[e];
    int d = dst[e];
    float nm = g_dinv[s] * w[e] * g_dinv[d];
    __half hn = __float2half(nm);
    unsigned packed = (unsigned)s | ((unsigned)*(unsigned short*)&hn << 16);
    int pos = atomicAdd(&g_cur[d], 1);
    g_csr[pos] = packed;
}

// ------- fused: gather-aggregate (CSR, fp16 msgs) + self + bias + LN ---------
__device__ __forceinline__ float4 ld_h16_row(const __half* H, int row, int lane) {
    uint2 u = *(const uint2*)(H + (size_t)row * 128 + lane * 4);
    float2 a = __half22float2(*(__half2*)&u.x);
    float2 b = __half22float2(*(__half2*)&u.y);
    return make_float4(a.x, a.y, b.x, b.y);
}
__device__ __forceinline__ float2 ld_h16_row64(const __half* H, int row, int lane) {
    uint32_t u = *(const uint32_t*)(H + (size_t)row * 64 + lane * 2);
    return __half22float2(*(__half2*)&u);
}
__device__ __forceinline__ void unpack_edge(unsigned p, int& s, float& nm) {
    s = (int)(p & 0xFFFFu);
    unsigned short hb = (unsigned short)(p >> 16);
    nm = __half2float(*(__half*)&hb);
}

template <int DIM, bool RELU, bool HALF_OUT>
__global__ void agg_ln_kernel(const __half* __restrict__ H, const float* __restrict__ b,
                              const float* __restrict__ gm, const float* __restrict__ bt,
                              void* __restrict__ Ov) {
    int gt = blockIdx.x * blockDim.x + threadIdx.x;
    int node = gt >> 5;
    if (node >= NNODES) return;
    int lane = gt & 31;

    float di = g_dinv[node];
    float d2 = di * di;
    int beg = g_off[node];
    int end = g_off[node + 1];

    if (DIM == 128) {
        int c = lane * 4;
        float4 hv = ld_h16_row(H, node, lane);
        float4 bv = *(const float4*)(b + c);
        float4 acc;
        acc.x = d2 * hv.x + bv.x;
        acc.y = d2 * hv.y + bv.y;
        acc.z = d2 * hv.z + bv.z;
        acc.w = d2 * hv.w + bv.w;

        int j = beg;
        for (; j + 3 < end; j += 4) {
            unsigned p0 = __ldg(&g_csr[j]);
            unsigned p1 = __ldg(&g_csr[j + 1]);
            unsigned p2 = __ldg(&g_csr[j + 2]);
            unsigned p3 = __ldg(&g_csr[j + 3]);
            int s0, s1, s2, s3;
            float n0, n1, n2, n3;
            unpack_edge(p0, s0, n0);
            unpack_edge(p1, s1, n1);
            unpack_edge(p2, s2, n2);
            unpack_edge(p3, s3, n3);
            float4 v0 = ld_h16_row(H, s0, lane);
            float4 v1 = ld_h16_row(H, s1, lane);
            float4 v2 = ld_h16_row(H, s2, lane);
            float4 v3 = ld_h16_row(H, s3, lane);
            acc.x += n0 * v0.x + n1 * v1.x + n2 * v2.x + n3 * v3.x;
            acc.y += n0 * v0.y + n1 * v1.y + n2 * v2.y + n3 * v3.y;
            acc.z += n0 * v0.z + n1 * v1.z + n2 * v2.z + n3 * v3.z;
            acc.w += n0 * v0.w + n1 * v1.w + n2 * v2.w + n3 * v3.w;
        }
        for (; j < end; j++) {
            unsigned p = __ldg(&g_csr[j]);
            int s;
            float nm;
            unpack_edge(p, s, nm);
            float4 v = ld_h16_row(H, s, lane);
            acc.x += nm * v.x;
            acc.y += nm * v.y;
            acc.z += nm * v.z;
            acc.w += nm * v.w;
        }

        float s1 = acc.x + acc.y + acc.z + acc.w;
        float s2 = acc.x * acc.x + acc.y * acc.y + acc.z * acc.z + acc.w * acc.w;
#pragma unroll
        for (int o = 16; o > 0; o >>= 1) {
            s1 += __shfl_xor_sync(0xffffffffu, s1, o);
            s2 += __shfl_xor_sync(0xffffffffu, s2, o);
        }
        float mean = s1 * (1.0f / 128.0f);
        float var = s2 * (1.0f / 128.0f) - mean * mean;
        float inv = rsqrtf(var + LN_EPS);
        float4 gv = *(const float4*)(gm + c);
        float4 tv = *(const float4*)(bt + c);
        float4 o4;
        o4.x = (acc.x - mean) * inv * gv.x + tv.x;
        o4.y = (acc.y - mean) * inv * gv.y + tv.y;
        o4.z = (acc.z - mean) * inv * gv.z + tv.z;
        o4.w = (acc.w - mean) * inv * gv.w + tv.w;
        if (RELU) {
            o4.x = fmaxf(o4.x, 0.0f);
            o4.y = fmaxf(o4.y, 0.0f);
            o4.z = fmaxf(o4.z, 0.0f);
            o4.w = fmaxf(o4.w, 0.0f);
        }
        if (HALF_OUT) {
            __half* O = (__half*)Ov;
            __half2 ha = __floats2half2_rn(o4.x, o4.y);
            __half2 hb = __floats2half2_rn(o4.z, o4.w);
            uint2 u;
            u.x = *(uint32_t*)&ha;
            u.y = *(uint32_t*)&hb;
            *(uint2*)(O + (size_t)node * 128 + c) = u;
        } else {
            float* O = (float*)Ov;
            *(float4*)(O + (size_t)node * 128 + c) = o4;
        }
    } else {   // DIM == 64
        int c = lane * 2;
        float2 hv = ld_h16_row64(H, node, lane);
        float2 bv = *(const float2*)(b + c);
        float2 acc;
        acc.x = d2 * hv.x + bv.x;
        acc.y = d2 * hv.y + bv.y;

        int j = beg;
        for (; j + 3 < end; j += 4) {
            unsigned p0 = __ldg(&g_csr[j]);
            unsigned p1 = __ldg(&g_csr[j + 1]);
            unsigned p2 = __ldg(&g_csr[j + 2]);
            unsigned p3 = __ldg(&g_csr[j + 3]);
            int s0, s1, s2, s3;
            float n0, n1, n2, n3;
            unpack_edge(p0, s0, n0);
            unpack_edge(p1, s1, n1);
            unpack_edge(p2, s2, n2);
            unpack_edge(p3, s3, n3);
            float2 v0 = ld_h16_row64(H, s0, lane);
            float2 v1 = ld_h16_row64(H, s1, lane);
            float2 v2 = ld_h16_row64(H, s2, lane);
            float2 v3 = ld_h16_row64(H, s3, lane);
            acc.x += n0 * v0.x + n1 * v1.x + n2 * v2.x + n3 * v3.x;
            acc.y += n0 * v0.y + n1 * v1.y + n2 * v2.y + n3 * v3.y;
        }
        for (; j < end; j++) {
            unsigned p = __ldg(&g_csr[j]);
            int s;
            float nm;
            unpack_edge(p, s, nm);
            float2 v = ld_h16_row64(H, s, lane);
            acc.x += nm * v.x;
            acc.y += nm * v.y;
        }

        float s1 = acc.x + acc.y;
        float s2 = acc.x * acc.x + acc.y * acc.y;
#pragma unroll
        for (int o = 16; o > 0; o >>= 1) {
            s1 += __shfl_xor_sync(0xffffffffu, s1, o);
            s2 += __shfl_xor_sync(0xffffffffu, s2, o);
        }
        float mean = s1 * (1.0f / 64.0f);
        float var = s2 * (1.0f / 64.0f) - mean * mean;
        float inv = rsqrtf(var + LN_EPS);
        float2 gv = *(const float2*)(gm + c);
        float2 tv = *(const float2*)(bt + c);
        float2 o2;
        o2.x = (acc.x - mean) * inv * gv.x + tv.x;
        o2.y = (acc.y - mean) * inv * gv.y + tv.y;
        if (RELU) {
            o2.x = fmaxf(o2.x, 0.0f);
            o2.y = fmaxf(o2.y, 0.0f);
        }
        float* O = (float*)Ov;
        *(float2*)(O + (size_t)node * 64 + c) = o2;
    }
}

// ---------------- host launch -------------------------------------------------
extern "C" void kernel_launch(void* const* d_in, const int* in_sizes, int n_in,
                              void* d_out, int out_size) {
    const float* x  = (const float*)d_in[0];
    const int*   ei = (const int*)d_in[1];
    const float* ew = (const float*)d_in[2];
    const float* W1 = (const float*)d_in[3];
    const float* b1 = (const float*)d_in[4];
    const float* g1 = (const float*)d_in[5];
    const float* t1 = (const float*)d_in[6];
    const float* W2 = (const float*)d_in[7];
    const float* b2 = (const float*)d_in[8];
    const float* g2 = (const float*)d_in[9];
    const float* t2 = (const float*)d_in[10];
    const float* W3 = (const float*)d_in[11];
    const float* b3 = (const float*)d_in[12];
    const float* g3 = (const float*)d_in[13];
    const float* t3 = (const float*)d_in[14];
    const int* src = ei;
    const int* dst = ei + NEDGES;

    __half *h16, *feat16, *w16_2, *w16_3;
    cudaGetSymbolAddress((void**)&h16, g_h16);
    cudaGetSymbolAddress((void**)&feat16, g_feat16);
    cudaGetSymbolAddress((void**)&w16_2, g_w16_2);
    cudaGetSymbolAddress((void**)&w16_3, g_w16_3);

    const int nblk_row = (NNODES * 32 + TB - 1) / TB;    // warp per node

    // precompute
    init_kernel<<<INIT_NB, TB>>>(W1, W2, W3);
    fused_gemm1_count_kernel<<<GEMM_NB + EDGE_NB, TB>>>(x, dst, ew);
    scan_block_kernel<<<SCAN_NB, SCAN_BS>>>();
    scan_add_kernel<<<SCAN_NB, SCAN_BS>>>();
    fill_kernel<<<EDGE_NB, TB>>>(src, dst, ew);

    // layer 1 aggregation (gemm1 already done in fused kernel)
    agg_ln_kernel<128, true, true><<<nblk_row, TB>>>(h16, b1, g1, t1, feat16);

    // layer 2
    gemm_kernel<128><<<GEMM_NB, TB>>>(feat16, w16_2, h16);
    agg_ln_kernel<128, true, true><<<nblk_row, TB>>>(h16, b2, g2, t2, feat16);

    // layer 3 (dout = 64, no relu), fp32 output straight to d_out
    gemm_kernel<64><<<GEMM_NB, TB>>>(feat16, w16_3, h16);
    agg_ln_kernel<64, false, false><<<nblk_row, TB>>>(h16, b3, g3, t3, d_out);
}

// round 14
// speedup vs baseline: 1.6200x; 1.0090x over previous
#include <cuda_runtime.h>
#include <cuda_fp16.h>
#include <mma.h>
#include <cstdint>

using namespace nvcuda;

#define NNODES 50000
#define NEDGES 800000
#define LN_EPS 1e-5f

#define SCAN_BS 512
#define SCAN_NB ((NNODES + SCAN_BS - 1) / SCAN_BS)   // 98
#define TB 256
#define GEMM_NB ((NNODES + 63) / 64)                 // 782
#define EDGE_NB ((NEDGES + TB - 1) / TB)             // 3125
#define INIT_NB ((2 * NNODES + TB - 1) / TB)         // 391

#define DEG_SCALE 1048576.0f        // 2^20 fixed-point for weighted degree
#define DEG_MASK  ((1ull << 44) - 1ull)
#define CNT_ONE   (1ull << 44)

// ---------------- scratch (static device globals; no runtime alloc) ----------
__device__ __align__(32) __half g_h16[NNODES * 128];    // GEMM output (fp16 messages)
__device__ __align__(32) __half g_feat16[NNODES * 128]; // LN output (fp16, next layer A)
__device__ __align__(32) __half g_w16_1[128 * 128];
__device__ __align__(32) __half g_w16_2[128 * 128];
__device__ __align__(32) __half g_w16_3[128 * 64];
__device__ __align__(16) unsigned long long g_degcnt[NNODES]; // bits[0:44)=deg*2^20, [44:64)=cnt
__device__ float  g_dinv[NNODES];
__device__ int    g_off[NNODES + 1];
__device__ int    g_cur[NNODES];
__device__ int    g_bsum[SCAN_NB];
__device__ unsigned g_csr[NEDGES];   // packed: low16 = src, high16 = fp16 norm

// ---------------- init: zero deg/cnt + convert weights to fp16 ---------------
__global__ void init_kernel(const float* __restrict__ W1, const float* __restrict__ W2,
                            const float* __restrict__ W3) {
    int i = blockIdx.x * blockDim.x + threadIdx.x;
    if (i < 2 * NNODES) ((int*)g_degcnt)[i] = 0;
    if (i < 16384) g_w16_1[i] = __float2half(W1[i]);
    else if (i < 32768) g_w16_2[i - 16384] = __float2half(W2[i - 16384]);
    else if (i < 40960) g_w16_3[i - 32768] = __float2half(W3[i - 32768]);
}

// ---------------- precompute bodies ------------------------------------------
__device__ __forceinline__ void count_body(const int* __restrict__ dst,
                                           const float* __restrict__ w, int blk) {
    int e = blk * TB + threadIdx.x;
    if (e < NEDGES) {
        int d = dst[e];
        unsigned long long inc =
            CNT_ONE | (unsigned long long)__float2uint_rn(w[e] * DEG_SCALE);
        atomicAdd(&g_degcnt[d], inc);   // ONE packed RMW per edge
    }
}

// ---------------- tensor-core GEMM body --------------------------------------
template <int OUT, bool A32>
__device__ __forceinline__ void gemm_body(const void* __restrict__ Av,
                                          const __half* __restrict__ W,
                                          __half* __restrict__ H, int blk) {
    constexpr int IN = 128;
    constexpr int ALD = IN + 16;
    constexpr int CLD = OUT + 8;
    constexpr int COLW = OUT / 2;
    constexpr int NF = COLW / 16;
    constexpr int ABYTES = 64 * ALD * 2;
    constexpr int CBYTES = 64 * CLD * 4;
    constexpr int BUFB = (ABYTES > CBYTES) ? ABYTES : CBYTES;

    __shared__ __align__(32) char buf[BUFB];
    __half (*As)[ALD] = (__half(*)[ALD])buf;
    float (*Cs)[CLD] = (float(*)[CLD])buf;

    const int t = threadIdx.x;
    const int row0 = blk * 64;

    if (A32) {
        const float* A = (const float*)Av;
        for (int i = t; i < 64 * (IN / 4); i += 256) {
            int r = i >> 5;
            int kc = (i & 31) * 4;
            int gr = row0 + r;
            float4 v = make_float4(0.f, 0.f, 0.f, 0.f);
            if (gr < NNODES) v = *(const float4*)(A + (size_t)gr * IN + kc);
            __half2 a = __floats2half2_rn(v.x, v.y);
            __half2 b = __floats2half2_rn(v.z, v.w);
            uint2 u;
            u.x = *(uint32_t*)&a;
            u.y = *(uint32_t*)&b;
            *(uint2*)&As[r][kc] = u;
        }
    } else {
        const __half* A = (const __half*)Av;
        for (int i = t; i < 64 * (IN / 8); i += 256) {
            int r = i >> 4;
            int kc = (i & 15) * 8;
            int gr = row0 + r;
            uint4 v = make_uint4(0u, 0u, 0u, 0u);
            if (gr < NNODES) v = *(const uint4*)(A + (size_t)gr * IN + kc);
            *(uint4*)&As[r][kc] = v;
        }
    }
    __syncthreads();

    const int w = t >> 5;
    const int wr = w >> 1;
    const int wc = w & 1;

    wmma::fragment<wmma::accumulator, 16, 16, 16, float> cf[NF];
#pragma unroll
    for (int j = 0; j < NF; j++) wmma::fill_fragment(cf[j], 0.0f);

    wmma::fragment<wmma::matrix_a, 16, 16, 16, __half, wmma::row_major> af;
    wmma::fragment<wmma::matrix_b, 16, 16, 16, __half, wmma::row_major> bf;

#pragma unroll
    for (int k = 0; k < IN; k += 16) {
        wmma::load_matrix_sync(af, &As[wr * 16][k], ALD);
#pragma unroll
        for (int j = 0; j < NF; j++) {
            wmma::load_matrix_sync(bf, W + (size_t)k * OUT + wc * COLW + j * 16, OUT);
            wmma::mma_sync(cf[j], af, bf, cf[j]);
        }
    }

    __syncthreads();
#pragma unroll
    for (int j = 0; j < NF; j++)
        wmma::store_matrix_sync(&Cs[wr * 16][wc * COLW + j * 16], cf[j], CLD,
                                wmma::mem_row_major);
    __syncthreads();

    for (int i = t; i < 64 * (OUT / 2); i += 256) {
        int r = i / (OUT / 2);
        int c = (i % (OUT / 2)) * 2;
        int gr = row0 + r;
        if (gr < NNODES) {
            __half2 hv = __floats2half2_rn(Cs[r][c], Cs[r][c + 1]);
            *(__half2*)(H + (size_t)gr * OUT + c) = hv;
        }
    }
}

// fused: gemm1 (blocks [0,GEMM_NB)) + count (blocks [GEMM_NB, GEMM_NB+EDGE_NB))
__global__ void __launch_bounds__(256) fused_gemm1_count_kernel(
    const float* __restrict__ x, const int* __restrict__ dst,
    const float* __restrict__ ew) {
    if (blockIdx.x < GEMM_NB) {
        gemm_body<128, true>(x, g_w16_1, g_h16, blockIdx.x);
    } else {
        count_body(dst, ew, blockIdx.x - GEMM_NB);
    }
}

template <int OUT>
__global__ void __launch_bounds__(256) gemm_kernel(const __half* __restrict__ A,
                                                   const __half* __restrict__ W,
                                                   __half* __restrict__ H) {
    gemm_body<OUT, false>(A, W, H, blockIdx.x);
}

// ---------------- scan --------------------------------------------------------
__global__ void scan_block_kernel() {
    __shared__ int wsum[SCAN_BS / 32];
    int t = threadIdx.x;
    int lane = t & 31;
    int wid = t >> 5;
    int i = blockIdx.x * SCAN_BS + t;
    int v = (i < NNODES) ? (int)(g_degcnt[i] >> 44) : 0;

    int x = v;
#pragma unroll
    for (int o = 1; o < 32; o <<= 1) {
        int y = __shfl_up_sync(0xffffffffu, x, o);
        if (lane >= o) x += y;
    }
    if (lane == 31) wsum[wid] = x;
    __syncthreads();
    if (wid == 0) {
        int s = (lane < SCAN_BS / 32) ? wsum[lane] : 0;
#pragma unroll
        for (int o = 1; o < SCAN_BS / 32; o <<= 1) {
            int y = __shfl_up_sync(0xffffffffu, s, o);
            if (lane >= o) s += y;
        }
        if (lane < SCAN_BS / 32) wsum[lane] = s;
    }
    __syncthreads();
    int wpre = (wid == 0) ? 0 : wsum[wid - 1];
    int excl = wpre + x - v;
    if (i < NNODES) g_off[i] = excl;
    if (t == SCAN_BS - 1) g_bsum[blockIdx.x] = wpre + x;
}

// scan_add with INLINE tops: each block warp-reduces g_bsum[0..bid) itself.
__global__ void scan_add_kernel() {
    __shared__ int s_pre;
    const int bid = blockIdx.x;
    if (threadIdx.x < 32) {
        int lane = threadIdx.x;
        int sum = 0;
        for (int k = lane; k < bid; k += 32) sum += g_bsum[k];
#pragma unroll
        for (int o = 16; o > 0; o >>= 1)
            sum += __shfl_xor_sync(0xffffffffu, sum, o);
        if (lane == 0) s_pre = sum;
    }
    __syncthreads();
    int i = bid * SCAN_BS + threadIdx.x;
    if (i < NNODES) {
        int off = g_off[i] + s_pre;
        g_off[i] = off;
        g_cur[i] = off;
        float deg = (float)(g_degcnt[i] & DEG_MASK) * (1.0f / DEG_SCALE);
        g_dinv[i] = rsqrtf(deg + 1.0f);   // +1 = self-loop weight
    }
    if (i == 0) g_off[NNODES] = NEDGES;
}

// fill: pack {fp16 norm | src16} into one word -> single 4B random store
__global__ void fill_kernel(const int* __restrict__ src, const int* __restrict__ dst,
                            const float* __restrict__ w) {
    int e = blockIdx.x * blockDim.x + threadIdx.x;
    if (e >= NEDGES) return;
    int s = src[e];
    int d = dst[e];
    float nm = g_dinv[s] * w[e] * g_dinv[d];
    __half hn = __float2half(nm);
    unsigned packed = (unsigned)s | ((unsigned)*(unsigned short*)&hn << 16);
    int pos = atomicAdd(&g_cur[d], 1);
    g_csr[pos] = packed;
}

// ------- fused: gather-aggregate (CSR, fp16 msgs) + self + bias + LN ---------
__device__ __forceinline__ float4 ld_h16_row(const __half* H, int row, int lane) {
    uint2 u = *(const uint2*)(H + (size_t)row * 128 + lane * 4);
    float2 a = __half22float2(*(__half2*)&u.x);
    float2 b = __half22float2(*(__half2*)&u.y);
    return make_float4(a.x, a.y, b.x, b.y);
}
__device__ __forceinline__ float2 ld_h16_row64(const __half* H, int row, int lane) {
    uint32_t u = *(const uint32_t*)(H + (size_t)row * 64 + lane * 2);
    return __half22float2(*(__half2*)&u);
}
__device__ __forceinline__ void unpack_edge(unsigned p, int& s, float& nm) {
    s = (int)(p & 0xFFFFu);
    unsigned short hb = (unsigned short)(p >> 16);
    nm = __half2float(*(__half*)&hb);
}

template <int DIM, bool RELU, bool HALF_OUT>
__global__ void agg_ln_kernel(const __half* __restrict__ H, const float* __restrict__ b,
                              const float* __restrict__ gm, const float* __restrict__ bt,
                              void* __restrict__ Ov) {
    int gt = blockIdx.x * blockDim.x + threadIdx.x;
    int node = gt >> 5;
    if (node >= NNODES) return;
    int lane = gt & 31;

    float di = g_dinv[node];
    float d2 = di * di;
    int beg = g_off[node];
    int end = g_off[node + 1];

    if (DIM == 128) {
        int c = lane * 4;
        float4 hv = ld_h16_row(H, node, lane);
        float4 bv = *(const float4*)(b + c);
        float4 acc;
        acc.x = d2 * hv.x + bv.x;
        acc.y = d2 * hv.y + bv.y;
        acc.z = d2 * hv.z + bv.z;
        acc.w = d2 * hv.w + bv.w;

        int j = beg;
        for (; j + 3 < end; j += 4) {
            unsigned p0 = __ldg(&g_csr[j]);
            unsigned p1 = __ldg(&g_csr[j + 1]);
            unsigned p2 = __ldg(&g_csr[j + 2]);
            unsigned p3 = __ldg(&g_csr[j + 3]);
            int s0, s1, s2, s3;
            float n0, n1, n2, n3;
            unpack_edge(p0, s0, n0);
            unpack_edge(p1, s1, n1);
            unpack_edge(p2, s2, n2);
            unpack_edge(p3, s3, n3);
            float4 v0 = ld_h16_row(H, s0, lane);
            float4 v1 = ld_h16_row(H, s1, lane);
            float4 v2 = ld_h16_row(H, s2, lane);
            float4 v3 = ld_h16_row(H, s3, lane);
            acc.x += n0 * v0.x + n1 * v1.x + n2 * v2.x + n3 * v3.x;
            acc.y += n0 * v0.y + n1 * v1.y + n2 * v2.y + n3 * v3.y;
            acc.z += n0 * v0.z + n1 * v1.z + n2 * v2.z + n3 * v3.z;
            acc.w += n0 * v0.w + n1 * v1.w + n2 * v2.w + n3 * v3.w;
        }
        for (; j < end; j++) {
            unsigned p = __ldg(&g_csr[j]);
            int s;
            float nm;
            unpack_edge(p, s, nm);
            float4 v = ld_h16_row(H, s, lane);
            acc.x += nm * v.x;
            acc.y += nm * v.y;
            acc.z += nm * v.z;
            acc.w += nm * v.w;
        }

        float s1 = acc.x + acc.y + acc.z + acc.w;
        float s2 = acc.x * acc.x + acc.y * acc.y + acc.z * acc.z + acc.w * acc.w;
#pragma unroll
        for (int o = 16; o > 0; o >>= 1) {
            s1 += __shfl_xor_sync(0xffffffffu, s1, o);
            s2 += __shfl_xor_sync(0xffffffffu, s2, o);
        }
        float mean = s1 * (1.0f / 128.0f);
        float var = s2 * (1.0f / 128.0f) - mean * mean;
        float inv = rsqrtf(var + LN_EPS);
        float4 gv = *(const float4*)(gm + c);
        float4 tv = *(const float4*)(bt + c);
        float4 o4;
        o4.x = (acc.x - mean) * inv * gv.x + tv.x;
        o4.y = (acc.y - mean) * inv * gv.y + tv.y;
        o4.z = (acc.z - mean) * inv * gv.z + tv.z;
        o4.w = (acc.w - mean) * inv * gv.w + tv.w;
        if (RELU) {
            o4.x = fmaxf(o4.x, 0.0f);
            o4.y = fmaxf(o4.y, 0.0f);
            o4.z = fmaxf(o4.z, 0.0f);
            o4.w = fmaxf(o4.w, 0.0f);
        }
        if (HALF_OUT) {
            __half* O = (__half*)Ov;
            __half2 ha = __floats2half2_rn(o4.x, o4.y);
            __half2 hb = __floats2half2_rn(o4.z, o4.w);
            uint2 u;
            u.x = *(uint32_t*)&ha;
            u.y = *(uint32_t*)&hb;
            *(uint2*)(O + (size_t)node * 128 + c) = u;
        } else {
            float* O = (float*)Ov;
            *(float4*)(O + (size_t)node * 128 + c) = o4;
        }
    } else {   // DIM == 64
        int c = lane * 2;
        float2 hv = ld_h16_row64(H, node, lane);
        float2 bv = *(const float2*)(b + c);
        float2 acc;
        acc.x = d2 * hv.x + bv.x;
        acc.y = d2 * hv.y + bv.y;

        int j = beg;
        for (; j + 3 < end; j += 4) {
            unsigned p0 = __ldg(&g_csr[j]);
            unsigned p1 = __ldg(&g_csr[j + 1]);
            unsigned p2 = __ldg(&g_csr[j + 2]);
            unsigned p3 = __ldg(&g_csr[j + 3]);
            int s0, s1, s2, s3;
            float n0, n1, n2, n3;
            unpack_edge(p0, s0, n0);
            unpack_edge(p1, s1, n1);
            unpack_edge(p2, s2, n2);
            unpack_edge(p3, s3, n3);
            float2 v0 = ld_h16_row64(H, s0, lane);
            float2 v1 = ld_h16_row64(H, s1, lane);
            float2 v2 = ld_h16_row64(H, s2, lane);
            float2 v3 = ld_h16_row64(H, s3, lane);
            acc.x += n0 * v0.x + n1 * v1.x + n2 * v2.x + n3 * v3.x;
            acc.y += n0 * v0.y + n1 * v1.y + n2 * v2.y + n3 * v3.y;
        }
        for (; j < end; j++) {
            unsigned p = __ldg(&g_csr[j]);
            int s;
            float nm;
            unpack_edge(p, s, nm);
            float2 v = ld_h16_row64(H, s, lane);
            acc.x += nm * v.x;
            acc.y += nm * v.y;
        }

        float s1 = acc.x + acc.y;
        float s2 = acc.x * acc.x + acc.y * acc.y;
#pragma unroll
        for (int o = 16; o > 0; o >>= 1) {
            s1 += __shfl_xor_sync(0xffffffffu, s1, o);
            s2 += __shfl_xor_sync(0xffffffffu, s2, o);
        }
        float mean = s1 * (1.0f / 64.0f);
        float var = s2 * (1.0f / 64.0f) - mean * mean;
        float inv = rsqrtf(var + LN_EPS);
        float2 gv = *(const float2*)(gm + c);
        float2 tv = *(const float2*)(bt + c);
        float2 o2;
        o2.x = (acc.x - mean) * inv * gv.x + tv.x;
        o2.y = (acc.y - mean) * inv * gv.y + tv.y;
        if (RELU) {
            o2.x = fmaxf(o2.x, 0.0f);
            o2.y = fmaxf(o2.y, 0.0f);
        }
        float* O = (float*)Ov;
        *(float2*)(O + (size_t)node * 64 + c) = o2;
    }
}

// ---------------- host launch -------------------------------------------------
extern "C" void kernel_launch(void* const* d_in, const int* in_sizes, int n_in,
                              void* d_out, int out_size) {
    const float* x  = (const float*)d_in[0];
    const int*   ei = (const int*)d_in[1];
    const float* ew = (const float*)d_in[2];
    const float* W1 = (const float*)d_in[3];
    const float* b1 = (const float*)d_in[4];
    const float* g1 = (const float*)d_in[5];
    const float* t1 = (const float*)d_in[6];
    const float* W2 = (const float*)d_in[7];
    const float* b2 = (const float*)d_in[8];
    const float* g2 = (const float*)d_in[9];
    const float* t2 = (const float*)d_in[10];
    const float* W3 = (const float*)d_in[11];
    const float* b3 = (const float*)d_in[12];
    const float* g3 = (const float*)d_in[13];
    const float* t3 = (const float*)d_in[14];
    const int* src = ei;
    const int* dst = ei + NEDGES;

    __half *h16, *feat16, *w16_2, *w16_3;
    cudaGetSymbolAddress((void**)&h16, g_h16);
    cudaGetSymbolAddress((void**)&feat16, g_feat16);
    cudaGetSymbolAddress((void**)&w16_2, g_w16_2);
    cudaGetSymbolAddress((void**)&w16_3, g_w16_3);

    const int nblk_row = (NNODES * 32 + TB - 1) / TB;    // warp per node

    // precompute
    init_kernel<<<INIT_NB, TB>>>(W1, W2, W3);
    fused_gemm1_count_kernel<<<GEMM_NB + EDGE_NB, TB>>>(x, dst, ew);
    scan_block_kernel<<<SCAN_NB, SCAN_BS>>>();
    scan_add_kernel<<<SCAN_NB, SCAN_BS>>>();
    fill_kernel<<<EDGE_NB, TB>>>(src, dst, ew);

    // layer 1 aggregation (gemm1 already done in fused kernel)
    agg_ln_kernel<128, true, true><<<nblk_row, TB>>>(h16, b1, g1, t1, feat16);

    // layer 2
    gemm_kernel<128><<<GEMM_NB, TB>>>(feat16, w16_2, h16);
    agg_ln_kernel<128, true, true><<<nblk_row, TB>>>(h16, b2, g2, t2, feat16);

    // layer 3 (dout = 64, no relu), fp32 output straight to d_out
    gemm_kernel<64><<<GEMM_NB, TB>>>(feat16, w16_3, h16);
    agg_ln_kernel<64, false, false><<<nblk_row, TB>>>(h16, b3, g3, t3, d_out);
}